// round 16
// baseline (speedup 1.0000x reference)
#include <cuda_runtime.h>
#include <cuda_fp16.h>

#define NU 50000
#define NI 50000
#define NN 100000            // NU + NI
#define D  64
#define K  4
#define E  1000000
#define NTOT (K * NN)        // 400000
#define CAP 64               // bucket capacity per row (deg ~ Poisson(20), max~47)

typedef unsigned long long ull;

#define FFMA2(acc, a, b) \
    asm("fma.rn.f32x2 %0, %1, %2, %0;" : "+l"(acc) : "l"(a), "l"(b))
#define FADD2(acc, b) \
    asm("add.rn.f32x2 %0, %0, %1;" : "+l"(acc) : "l"(b))
#define PACK2(dst, lo, hi) \
    asm("mov.b64 %0, {%1, %2};" : "=l"(dst) : "f"(lo), "f"(hi))
#define UNPACK2(lo, hi, src) \
    asm("mov.b64 {%0, %1}, %2;" : "=f"(lo), "=f"(hi) : "l"(src))

// single fp16 row load + packed f32x2 accumulate
#define GLOADH(srcp, n, f, acc01, acc23)                                   \
    do {                                                                   \
        uint2 raw = *(const uint2*)((srcp) + (size_t)(n) * D + (f));       \
        float2 lo = __half22float2(*(const __half2*)&raw.x);               \
        float2 hi = __half22float2(*(const __half2*)&raw.y);               \
        FADD2(acc01, *(const ull*)&lo);                                    \
        FADD2(acc23, *(const ull*)&hi);                                    \
    } while (0)

// pairwise: fp16 add two neighbor rows, then convert + accumulate in fp32
#define GPAIR(rA, rB, acc01, acc23)                                       \
    do {                                                                   \
        __half2 sx = __hadd2(*(const __half2*)&(rA).x,                     \
                             *(const __half2*)&(rB).x);                    \
        __half2 sy = __hadd2(*(const __half2*)&(rA).y,                     \
                             *(const __half2*)&(rB).y);                    \
        float2 lo = __half22float2(sx);                                    \
        float2 hi = __half22float2(sy);                                    \
        FADD2(acc01, *(const ull*)&lo);                                    \
        FADD2(acc23, *(const ull*)&hi);                                    \
    } while (0)

__device__ __forceinline__ float tanhf_fast(float x) {
    float y;
    asm("tanh.approx.f32 %0, %1;" : "=f"(y) : "f"(x));
    return y;
}

// ---------------- device scratch (g_cursor re-zeroed by memset each launch) --
__device__ int    g_cursor[NTOT];          // fill cursor == degree after fill
__device__ int    g_col[(size_t)NTOT * CAP];   // bucketized CSR neighbor ids
__device__ float  g_dinv[NTOT];
__device__ float  g_xc[NN * D];      // current x fp32 (gate/output path)
__device__ __half g_gh[NN * D];      // dinv ⊙ (relu(xc)+bias) fp16 (spmm1 operand)
__device__ __half g_eh[NN * D];      // dinv ⊙ edge fp16 (spmm2 operand)
__device__ float  g_g[NN * D];       // node_pre fp32 (mega input)
__device__ float  g_hx[NN * D];      // hidden_x pre-tanh, pair-packed layout:
                                     // [(row>>1)*128 + j*2 + (row&1)]

// ---------------- bucket fill: direct scatter, no count/scan -----------------
__global__ void fill_bucket_kernel(const int* __restrict__ rows,
                                   const int* __restrict__ cols) {
    int idx = blockIdx.x * blockDim.x + threadIdx.x;
    if (idx >= K * E) return;
    int base = (idx / E) * NN;
    int r = rows[idx];
    int c = cols[idx];
    int rp1 = base + r;
    int rp2 = base + NU + c;
    int p1 = atomicAdd(g_cursor + rp1, 1);
    if (p1 < CAP) g_col[(size_t)rp1 * CAP + p1] = NU + c;
    int p2 = atomicAdd(g_cursor + rp2, 1);
    if (p2 < CAP) g_col[(size_t)rp2 * CAP + p2] = r;
}

// ---------------- dinv (all K) + g_gh init for k=0, one kernel ---------------
__global__ void dinv_g_kernel(const float* __restrict__ x,
                              const float* __restrict__ bias) {
    int idx = blockIdx.x * blockDim.x + threadIdx.x;
    if (idx < NTOT)
        g_dinv[idx] = rsqrtf((float)g_cursor[idx] + 1e-7f);
    if (idx >= NN * 16) return;
    int i = idx >> 4;
    int q = (idx & 15) << 2;
    float di = rsqrtf((float)g_cursor[i] + 1e-7f);   // subgraph 0, local
    float4 xv = *(const float4*)(x + (size_t)i * D + q);
    float4 b  = *(const float4*)(bias + q);
    __half2 h01 = __floats2half2_rn(di * (fmaxf(xv.x, 0.f) + b.x),
                                    di * (fmaxf(xv.y, 0.f) + b.y));
    __half2 h23 = __floats2half2_rn(di * (fmaxf(xv.z, 0.f) + b.z),
                                    di * (fmaxf(xv.w, 0.f) + b.w));
    uint2 raw;
    raw.x = *(const unsigned*)&h01;
    raw.y = *(const unsigned*)&h23;
    *(uint2*)(g_gh + (size_t)i * D + q) = raw;
}

// ---------------- fp16 bucket gather (half-warp layout + pairwise hadd2) -----
// out_f32[i] = dinv[i] * sum_n src[n];  if out_h: out_h = dinv[i]*out_f32[i]
__global__ void __launch_bounds__(256)
gather_kernel(const __half* __restrict__ src,
              float* __restrict__ out_f32,
              __half* __restrict__ out_h, int k) {
    int gw = (blockIdx.x * blockDim.x + threadIdx.x) >> 5;
    if (gw >= NN) return;
    int lane = threadIdx.x & 31;
    int sub  = lane & 15;
    int half_id = lane >> 4;
    int f = sub << 2;
    int rp = k * NN + gw;
    int deg = g_cursor[rp];
    if (deg > CAP) deg = CAP;
    int beg = rp * CAP;
    int end = beg + deg;

    ull acc01 = 0ull, acc23 = 0ull;

    int p = beg + half_id;
    for (; p + 14 < end; p += 16) {
        int n[8];
#pragma unroll
        for (int j = 0; j < 8; j++) n[j] = __ldg(g_col + p + 2 * j);
        uint2 raw[8];
#pragma unroll
        for (int j = 0; j < 8; j++)
            raw[j] = *(const uint2*)(src + (size_t)n[j] * D + f);
#pragma unroll
        for (int j = 0; j < 4; j++)
            GPAIR(raw[2 * j], raw[2 * j + 1], acc01, acc23);
    }
    for (; p + 6 < end; p += 8) {
        int n0 = __ldg(g_col + p);
        int n1 = __ldg(g_col + p + 2);
        int n2 = __ldg(g_col + p + 4);
        int n3 = __ldg(g_col + p + 6);
        uint2 r0 = *(const uint2*)(src + (size_t)n0 * D + f);
        uint2 r1 = *(const uint2*)(src + (size_t)n1 * D + f);
        uint2 r2 = *(const uint2*)(src + (size_t)n2 * D + f);
        uint2 r3 = *(const uint2*)(src + (size_t)n3 * D + f);
        GPAIR(r0, r1, acc01, acc23);
        GPAIR(r2, r3, acc01, acc23);
    }
    for (; p < end; p += 2) {
        int n = __ldg(g_col + p);
        GLOADH(src, n, f, acc01, acc23);
    }

    float a0, a1, a2, a3;
    UNPACK2(a0, a1, acc01);
    UNPACK2(a2, a3, acc23);
    a0 += __shfl_xor_sync(0xffffffffu, a0, 16);
    a1 += __shfl_xor_sync(0xffffffffu, a1, 16);
    a2 += __shfl_xor_sync(0xffffffffu, a2, 16);
    a3 += __shfl_xor_sync(0xffffffffu, a3, 16);

    if (half_id == 0) {
        float di = g_dinv[rp];
        float4 e = make_float4(di * a0, di * a1, di * a2, di * a3);
        *(float4*)(out_f32 + (size_t)gw * D + f) = e;
        if (out_h) {
            __half2 h01 = __floats2half2_rn(di * e.x, di * e.y);
            __half2 h23 = __floats2half2_rn(di * e.z, di * e.w);
            uint2 raw;
            raw.x = *(const unsigned*)&h01;
            raw.y = *(const unsigned*)&h23;
            *(uint2*)(out_h + (size_t)gw * D + f) = raw;
        }
    }
}

// ---------------- mega v6: v3 shell + chained hidden_x -----------------------
// has_hx: load pre-tanh hidden_x from g_hx (skip fusion-x GEMV).
// knext>=0: emit g_gh and packed next hidden_x = a·hx + (1-a)·hn (pre-tanh).
__global__ void __launch_bounds__(256)
mega_kernel(const float* __restrict__ fc1_W,
            const float* __restrict__ W1,
            const float* __restrict__ b1,
            const float* __restrict__ w2,
            const float* __restrict__ hbias,
            const float* __restrict__ xc_src,
            float* __restrict__ out_nodes, int has_hx, int knext) {
    __shared__ float Wt1[64 * 64];   // Wt1[d*64+j] = fc1_W[j][d]
    __shared__ float Wtf[64 * 64];
    __shared__ float b1s[64], w2s[64], biass[64];
    __shared__ float SP[8][2][128];  // softmax rows, pair-packed
    __shared__ float XP[8][2][128];  // x rows, pair-packed (k=0 GEMV only)
    __shared__ float NP[8][2][128];  // fc1 output rows, pair-packed

    int tid = threadIdx.x;
    for (int i = tid; i < 4096; i += 256) {
        int d = i >> 6, j = i & 63;
        Wt1[i] = fc1_W[j * 64 + d];
        Wtf[i] = W1[j * 64 + d];
    }
    if (tid < 64) {
        b1s[tid]   = b1[tid];
        w2s[tid]   = w2[tid];
        biass[tid] = hbias[tid];
    }
    __syncthreads();

    int warp = tid >> 5, lane = tid & 31;
    int lane2 = lane * 2;

    for (int row0 = blockIdx.x * 32 + warp * 4; row0 < NN; row0 += gridDim.x * 32) {
        float xr[2][4];   // [pair][(x_r0_d0, x_r1_d0, x_r0_d1, x_r1_d1)]

        // ---- stage: softmax rows + x rows, pair-packed ----
#pragma unroll
        for (int p = 0; p < 2; p++) {
            float s0[2], s1[2];
#pragma unroll
            for (int r = 0; r < 2; r++) {
                int row = row0 + p * 2 + r;
                float2 v = *(const float2*)(g_g + (size_t)row * D + lane2);
                float m = fmaxf(v.x, v.y);
#pragma unroll
                for (int o = 16; o; o >>= 1)
                    m = fmaxf(m, __shfl_xor_sync(0xffffffffu, m, o));
                float e0 = __expf(v.x - m), e1 = __expf(v.y - m);
                float s = e0 + e1;
#pragma unroll
                for (int o = 16; o; o >>= 1)
                    s += __shfl_xor_sync(0xffffffffu, s, o);
                float inv = 1.0f / s;
                s0[r] = e0 * inv;
                s1[r] = e1 * inv;
                float2 vx = *(const float2*)(xc_src + (size_t)row * D + lane2);
                xr[p][r]     = vx.x;
                xr[p][r + 2] = vx.y;
            }
            *(float4*)&SP[warp][p][lane2 * 2] = make_float4(s0[0], s0[1], s1[0], s1[1]);
            if (!has_hx)
                *(float4*)&XP[warp][p][lane2 * 2] =
                    make_float4(xr[p][0], xr[p][1], xr[p][2], xr[p][3]);
        }
        __syncwarp();

        // ---- fc1: 4 rows, packed across each row pair ----
        ull a00 = 0ull, a01 = 0ull, a10 = 0ull, a11 = 0ull;
#pragma unroll 16
        for (int d = 0; d < 64; d++) {
            ull w = *(const ull*)&Wt1[d * 64 + lane2];
            float wlo, whi;
            UNPACK2(wlo, whi, w);
            ull w0d, w1d;
            PACK2(w0d, wlo, wlo);
            PACK2(w1d, whi, whi);
            ull sp0 = *(const ull*)&SP[warp][0][d * 2];
            ull sp1 = *(const ull*)&SP[warp][1][d * 2];
            FFMA2(a00, sp0, w0d);
            FFMA2(a01, sp0, w1d);
            FFMA2(a10, sp1, w0d);
            FFMA2(a11, sp1, w1d);
        }
        {
            ulonglong2 n0; n0.x = a00; n0.y = a01;
            ulonglong2 n1; n1.x = a10; n1.y = a11;
            *(ulonglong2*)&NP[warp][0][lane2 * 2] = n0;
            *(ulonglong2*)&NP[warp][1][lane2 * 2] = n1;
        }
        __syncwarp();

        // ---- fusion hiddens (pre-tanh, packed over row pairs) ----
        ull bj0, bj1;
        PACK2(bj0, b1s[lane2], b1s[lane2]);
        PACK2(bj1, b1s[lane2 + 1], b1s[lane2 + 1]);
        ull hx00, hx01, hx10, hx11;
        ull hn00 = bj0, hn01 = bj1, hn10 = bj0, hn11 = bj1;

        if (has_hx) {
            // hidden_x chained from previous step (pre-tanh, pair-packed)
            size_t pbase = (size_t)(row0 >> 1) * 128 + lane * 4;
            ulonglong2 t0 = *(const ulonglong2*)&g_hx[pbase];
            ulonglong2 t1 = *(const ulonglong2*)&g_hx[pbase + 128];
            hx00 = t0.x; hx01 = t0.y; hx10 = t1.x; hx11 = t1.y;
            // hidden_n GEMV only
#pragma unroll 16
            for (int d = 0; d < 64; d++) {
                ull w = *(const ull*)&Wtf[d * 64 + lane2];
                float wlo, whi;
                UNPACK2(wlo, whi, w);
                ull v0d, v1d;
                PACK2(v0d, wlo, wlo);
                PACK2(v1d, whi, whi);
                ull n0 = *(const ull*)&NP[warp][0][d * 2];
                ull n1 = *(const ull*)&NP[warp][1][d * 2];
                FFMA2(hn00, n0, v0d);
                FFMA2(hn01, n0, v1d);
                FFMA2(hn10, n1, v0d);
                FFMA2(hn11, n1, v1d);
            }
        } else {
            hx00 = bj0; hx01 = bj1; hx10 = bj0; hx11 = bj1;
#pragma unroll 16
            for (int d = 0; d < 64; d++) {
                ull w = *(const ull*)&Wtf[d * 64 + lane2];
                float wlo, whi;
                UNPACK2(wlo, whi, w);
                ull v0d, v1d;
                PACK2(v0d, wlo, wlo);
                PACK2(v1d, whi, whi);
                ull x0 = *(const ull*)&XP[warp][0][d * 2];
                ull x1 = *(const ull*)&XP[warp][1][d * 2];
                ull n0 = *(const ull*)&NP[warp][0][d * 2];
                ull n1 = *(const ull*)&NP[warp][1][d * 2];
                FFMA2(hx00, x0, v0d);
                FFMA2(hx01, x0, v1d);
                FFMA2(hx10, x1, v0d);
                FFMA2(hx11, x1, v1d);
                FFMA2(hn00, n0, v0d);
                FFMA2(hn01, n0, v1d);
                FFMA2(hn10, n1, v0d);
                FFMA2(hn11, n1, v1d);
            }
        }

        // ---- scores, gate, blend, stores (per pair) ----
        float w2a = w2s[lane2], w2b = w2s[lane2 + 1];
        ull haccx[2][2] = {{hx00, hx01}, {hx10, hx11}};
        ull haccn[2][2] = {{hn00, hn01}, {hn10, hn11}};
        ull naccs[2][2] = {{a00, a01}, {a10, a11}};
        float bb0 = biass[lane2], bb1 = biass[lane2 + 1];
#pragma unroll
        for (int p = 0; p < 2; p++) {
            float hx0lo, hx0hi, hx1lo, hx1hi, hn0lo, hn0hi, hn1lo, hn1hi;
            UNPACK2(hx0lo, hx0hi, haccx[p][0]);
            UNPACK2(hx1lo, hx1hi, haccx[p][1]);
            UNPACK2(hn0lo, hn0hi, haccn[p][0]);
            UNPACK2(hn1lo, hn1hi, haccn[p][1]);
            float sxr0 = tanhf_fast(hx0lo) * w2a + tanhf_fast(hx1lo) * w2b;
            float sxr1 = tanhf_fast(hx0hi) * w2a + tanhf_fast(hx1hi) * w2b;
            float snr0 = tanhf_fast(hn0lo) * w2a + tanhf_fast(hn1lo) * w2b;
            float snr1 = tanhf_fast(hn0hi) * w2a + tanhf_fast(hn1hi) * w2b;
#pragma unroll
            for (int o = 16; o; o >>= 1) {
                sxr0 += __shfl_xor_sync(0xffffffffu, sxr0, o);
                sxr1 += __shfl_xor_sync(0xffffffffu, sxr1, o);
                snr0 += __shfl_xor_sync(0xffffffffu, snr0, o);
                snr1 += __shfl_xor_sync(0xffffffffu, snr1, o);
            }
            float aR0 = 1.0f / (1.0f + __expf(snr0 - sxr0));
            float aR1 = 1.0f / (1.0f + __expf(snr1 - sxr1));

            float n0lo, n0hi, n1lo, n1hi;
            UNPACK2(n0lo, n0hi, naccs[p][0]);
            UNPACK2(n1lo, n1hi, naccs[p][1]);

            int rowA = row0 + p * 2;
            int rowB = rowA + 1;
            float oA0 = aR0 * xr[p][0] + (1.f - aR0) * n0lo;
            float oA1 = aR0 * xr[p][2] + (1.f - aR0) * n1lo;
            float oB0 = aR1 * xr[p][1] + (1.f - aR1) * n0hi;
            float oB1 = aR1 * xr[p][3] + (1.f - aR1) * n1hi;

            *(float2*)(out_nodes + (size_t)rowA * D + lane2) = make_float2(oA0, oA1);
            *(float2*)(g_xc + (size_t)rowA * D + lane2)      = make_float2(oA0, oA1);
            *(float2*)(out_nodes + (size_t)rowB * D + lane2) = make_float2(oB0, oB1);
            *(float2*)(g_xc + (size_t)rowB * D + lane2)      = make_float2(oB0, oB1);
            if (knext >= 0) {
                float dA = __ldg(g_dinv + knext * NN + rowA);
                float dB = __ldg(g_dinv + knext * NN + rowB);
                *(__half2*)(g_gh + (size_t)rowA * D + lane2) = __floats2half2_rn(
                    dA * (fmaxf(oA0, 0.f) + bb0), dA * (fmaxf(oA1, 0.f) + bb1));
                *(__half2*)(g_gh + (size_t)rowB * D + lane2) = __floats2half2_rn(
                    dB * (fmaxf(oB0, 0.f) + bb0), dB * (fmaxf(oB1, 0.f) + bb1));
                // next hidden_x (pre-tanh): a·hx + (1-a)·hn, packed over rows
                ull apk, bpk;
                PACK2(apk, aR0, aR1);
                PACK2(bpk, 1.f - aR0, 1.f - aR1);
                ull h0 = 0ull, h1 = 0ull;
                FFMA2(h0, apk, haccx[p][0]);
                FFMA2(h0, bpk, haccn[p][0]);
                FFMA2(h1, apk, haccx[p][1]);
                FFMA2(h1, bpk, haccn[p][1]);
                ulonglong2 st; st.x = h0; st.y = h1;
                *(ulonglong2*)&g_hx[(size_t)((row0 >> 1) + p) * 128 + lane * 4] = st;
            }
        }
    }
}

// ---------------- launch ------------------------------------------------------
extern "C" void kernel_launch(void* const* d_in, const int* in_sizes, int n_in,
                              void* d_out, int out_size) {
    const float* x         = (const float*)d_in[0];
    const float* hgc1_bias = (const float*)d_in[1];
    const float* fc1_W     = (const float*)d_in[2];
    const float* fus_l1_W  = (const float*)d_in[3];
    const float* fus_l1_b  = (const float*)d_in[4];
    const float* fus_l2_W  = (const float*)d_in[5];
    // d_in[6] = fus_l2_b : cancels in the 2-way softmax
    const int* rows = (const int*)d_in[7];
    const int* cols = (const int*)d_in[8];

    float* out_nodes = (float*)d_out;
    float* out_edges = (float*)d_out + (size_t)K * NN * D;

    float *xc_p = nullptr, *g_p = nullptr;
    __half *gh_p = nullptr, *eh_p = nullptr;
    int* cur_p = nullptr;
    cudaGetSymbolAddress((void**)&xc_p, g_xc);
    cudaGetSymbolAddress((void**)&gh_p, g_gh);
    cudaGetSymbolAddress((void**)&eh_p, g_eh);
    cudaGetSymbolAddress((void**)&g_p, g_g);
    cudaGetSymbolAddress((void**)&cur_p, g_cursor);

    // bucket-CSR build: memset + fill; dinv fused with g_gh init
    cudaMemsetAsync(cur_p, 0, (size_t)NTOT * sizeof(int));
    fill_bucket_kernel<<<(K * E + 255) / 256, 256>>>(rows, cols);
    dinv_g_kernel<<<(NN * 16 + 255) / 256, 256>>>(x, hgc1_bias);

    const int SPMM_BLOCKS = NN / 8;     // 12500 (warp per row)
    const int MEGA_BLOCKS = 592;        // persistent grid-stride, 4 CTAs/SM

    for (int k = 0; k < K; k++) {
        float* edge_k = out_edges + (size_t)k * NN * D;
        const float* xc_src = (k == 0) ? x : xc_p;
        // spmm1: edge = Â gh ; g_eh = dinv ⊙ edge (fp16)
        gather_kernel<<<SPMM_BLOCKS, 256>>>(gh_p, edge_k, eh_p, k);
        // spmm2: node_pre = Â (dinv ⊙ edge) -> g_g (fp32)
        gather_kernel<<<SPMM_BLOCKS, 256>>>(eh_p, g_p, nullptr, k);
        // epilogue: softmax + fc1 + fusion gate (+ gh, hidden_x for next step)
        mega_kernel<<<MEGA_BLOCKS, 256>>>(
            fc1_W, fus_l1_W, fus_l1_b, fus_l2_W, hgc1_bias, xc_src,
            out_nodes + (size_t)k * NN * D, (k == 0) ? 0 : 1,
            (k + 1 < K) ? (k + 1) : -1);
    }
}

// round 17
// speedup vs baseline: 1.0412x; 1.0412x over previous
#include <cuda_runtime.h>
#include <cuda_fp16.h>

#define NU 50000
#define NI 50000
#define NN 100000            // NU + NI
#define D  64
#define K  4
#define E  1000000
#define NTOT (K * NN)        // 400000
#define CAP 64               // bucket capacity per row (deg ~ Poisson(20), max~47)

typedef unsigned long long ull;

#define FFMA2(acc, a, b) \
    asm("fma.rn.f32x2 %0, %1, %2, %0;" : "+l"(acc) : "l"(a), "l"(b))
#define FADD2(acc, b) \
    asm("add.rn.f32x2 %0, %0, %1;" : "+l"(acc) : "l"(b))
#define PACK2(dst, lo, hi) \
    asm("mov.b64 %0, {%1, %2};" : "=l"(dst) : "f"(lo), "f"(hi))
#define UNPACK2(lo, hi, src) \
    asm("mov.b64 {%0, %1}, %2;" : "=f"(lo), "=f"(hi) : "l"(src))

// single fp16 row load + packed f32x2 accumulate
#define GLOADH(srcp, n, f, acc01, acc23)                                   \
    do {                                                                   \
        uint2 raw = *(const uint2*)((srcp) + (size_t)(n) * D + (f));       \
        float2 lo = __half22float2(*(const __half2*)&raw.x);               \
        float2 hi = __half22float2(*(const __half2*)&raw.y);               \
        FADD2(acc01, *(const ull*)&lo);                                    \
        FADD2(acc23, *(const ull*)&hi);                                    \
    } while (0)

// pairwise: fp16 add two neighbor rows, then convert + accumulate in fp32
#define GPAIR(rA, rB, acc01, acc23)                                       \
    do {                                                                   \
        __half2 sx = __hadd2(*(const __half2*)&(rA).x,                     \
                             *(const __half2*)&(rB).x);                    \
        __half2 sy = __hadd2(*(const __half2*)&(rA).y,                     \
                             *(const __half2*)&(rB).y);                    \
        float2 lo = __half22float2(sx);                                    \
        float2 hi = __half22float2(sy);                                    \
        FADD2(acc01, *(const ull*)&lo);                                    \
        FADD2(acc23, *(const ull*)&hi);                                    \
    } while (0)

__device__ __forceinline__ float tanhf_fast(float x) {
    float y;
    asm("tanh.approx.f32 %0, %1;" : "=f"(y) : "f"(x));
    return y;
}

// ---------------- device scratch (g_cursor re-zeroed by memset each launch) --
__device__ int    g_cursor[NTOT];          // fill cursor == degree after fill
__device__ int    g_col[(size_t)NTOT * CAP];   // bucketized CSR neighbor ids
__device__ float  g_dinv[NTOT];
__device__ float  g_xc[NN * D];      // current x fp32 (gate/output path)
__device__ __half g_gh[NN * D];      // dinv ⊙ (relu(xc)+bias) fp16 (spmm1 operand)
__device__ __half g_eh[NN * D];      // dinv ⊙ edge fp16 (spmm2 operand)
__device__ __half g_gp[NN * D];      // node_pre fp16 (mega softmax input)

// ---------------- bucket fill: direct scatter, no count/scan -----------------
__global__ void fill_bucket_kernel(const int* __restrict__ rows,
                                   const int* __restrict__ cols) {
    int idx = blockIdx.x * blockDim.x + threadIdx.x;
    if (idx >= K * E) return;
    int base = (idx / E) * NN;
    int r = rows[idx];
    int c = cols[idx];
    int rp1 = base + r;
    int rp2 = base + NU + c;
    int p1 = atomicAdd(g_cursor + rp1, 1);
    if (p1 < CAP) g_col[(size_t)rp1 * CAP + p1] = NU + c;
    int p2 = atomicAdd(g_cursor + rp2, 1);
    if (p2 < CAP) g_col[(size_t)rp2 * CAP + p2] = r;
}

// ---------------- dinv (all K) + g_gh init for k=0, one kernel ---------------
__global__ void dinv_g_kernel(const float* __restrict__ x,
                              const float* __restrict__ bias) {
    int idx = blockIdx.x * blockDim.x + threadIdx.x;
    if (idx < NTOT)
        g_dinv[idx] = rsqrtf((float)g_cursor[idx] + 1e-7f);
    if (idx >= NN * 16) return;
    int i = idx >> 4;
    int q = (idx & 15) << 2;
    float di = rsqrtf((float)g_cursor[i] + 1e-7f);   // subgraph 0, local
    float4 xv = *(const float4*)(x + (size_t)i * D + q);
    float4 b  = *(const float4*)(bias + q);
    __half2 h01 = __floats2half2_rn(di * (fmaxf(xv.x, 0.f) + b.x),
                                    di * (fmaxf(xv.y, 0.f) + b.y));
    __half2 h23 = __floats2half2_rn(di * (fmaxf(xv.z, 0.f) + b.z),
                                    di * (fmaxf(xv.w, 0.f) + b.w));
    uint2 raw;
    raw.x = *(const unsigned*)&h01;
    raw.y = *(const unsigned*)&h23;
    *(uint2*)(g_gh + (size_t)i * D + q) = raw;
}

// ---------------- fp16 bucket gather (half-warp layout + pairwise hadd2) -----
// e = dinv[i] * sum_n src[n]
// if out_f32: store e fp32;  if out_h: store (extra_di ? dinv[i]*e : e) fp16
__global__ void __launch_bounds__(256)
gather_kernel(const __half* __restrict__ src,
              float* __restrict__ out_f32,
              __half* __restrict__ out_h, int extra_di, int k) {
    int gw = (blockIdx.x * blockDim.x + threadIdx.x) >> 5;
    if (gw >= NN) return;
    int lane = threadIdx.x & 31;
    int sub  = lane & 15;
    int half_id = lane >> 4;
    int f = sub << 2;
    int rp = k * NN + gw;
    int deg = g_cursor[rp];
    if (deg > CAP) deg = CAP;
    int beg = rp * CAP;
    int end = beg + deg;

    ull acc01 = 0ull, acc23 = 0ull;

    int p = beg + half_id;
    for (; p + 14 < end; p += 16) {
        int n[8];
#pragma unroll
        for (int j = 0; j < 8; j++) n[j] = __ldg(g_col + p + 2 * j);
        uint2 raw[8];
#pragma unroll
        for (int j = 0; j < 8; j++)
            raw[j] = *(const uint2*)(src + (size_t)n[j] * D + f);
#pragma unroll
        for (int j = 0; j < 4; j++)
            GPAIR(raw[2 * j], raw[2 * j + 1], acc01, acc23);
    }
    for (; p + 6 < end; p += 8) {
        int n0 = __ldg(g_col + p);
        int n1 = __ldg(g_col + p + 2);
        int n2 = __ldg(g_col + p + 4);
        int n3 = __ldg(g_col + p + 6);
        uint2 r0 = *(const uint2*)(src + (size_t)n0 * D + f);
        uint2 r1 = *(const uint2*)(src + (size_t)n1 * D + f);
        uint2 r2 = *(const uint2*)(src + (size_t)n2 * D + f);
        uint2 r3 = *(const uint2*)(src + (size_t)n3 * D + f);
        GPAIR(r0, r1, acc01, acc23);
        GPAIR(r2, r3, acc01, acc23);
    }
    for (; p < end; p += 2) {
        int n = __ldg(g_col + p);
        GLOADH(src, n, f, acc01, acc23);
    }

    float a0, a1, a2, a3;
    UNPACK2(a0, a1, acc01);
    UNPACK2(a2, a3, acc23);
    a0 += __shfl_xor_sync(0xffffffffu, a0, 16);
    a1 += __shfl_xor_sync(0xffffffffu, a1, 16);
    a2 += __shfl_xor_sync(0xffffffffu, a2, 16);
    a3 += __shfl_xor_sync(0xffffffffu, a3, 16);

    if (half_id == 0) {
        float di = g_dinv[rp];
        float4 e = make_float4(di * a0, di * a1, di * a2, di * a3);
        if (out_f32)
            *(float4*)(out_f32 + (size_t)gw * D + f) = e;
        if (out_h) {
            float s = extra_di ? di : 1.0f;
            __half2 h01 = __floats2half2_rn(s * e.x, s * e.y);
            __half2 h23 = __floats2half2_rn(s * e.z, s * e.w);
            uint2 raw;
            raw.x = *(const unsigned*)&h01;
            raw.y = *(const unsigned*)&h23;
            *(uint2*)(out_h + (size_t)gw * D + f) = raw;
        }
    }
}

// ---------------- mega v3 (proven R13/R15): 4 rows/warp, pair-packed GEMVs ---
// node_pre now fp16 (g_gp). Static smem ~45KB -> 4 CTAs/SM.
__global__ void __launch_bounds__(256)
mega_kernel(const float* __restrict__ fc1_W,
            const float* __restrict__ W1,
            const float* __restrict__ b1,
            const float* __restrict__ w2,
            const float* __restrict__ hbias,
            const float* __restrict__ xc_src,
            float* __restrict__ out_nodes, int knext) {
    __shared__ float Wt1[64 * 64];   // Wt1[d*64+j] = fc1_W[j][d]
    __shared__ float Wtf[64 * 64];
    __shared__ float b1s[64], w2s[64], biass[64];
    __shared__ float SP[8][2][128];  // softmax rows, pair-packed
    __shared__ float XP[8][2][128];  // x rows, pair-packed
    __shared__ float NP[8][2][128];  // fc1 output rows, pair-packed

    int tid = threadIdx.x;
    for (int i = tid; i < 4096; i += 256) {
        int d = i >> 6, j = i & 63;
        Wt1[i] = fc1_W[j * 64 + d];
        Wtf[i] = W1[j * 64 + d];
    }
    if (tid < 64) {
        b1s[tid]   = b1[tid];
        w2s[tid]   = w2[tid];
        biass[tid] = hbias[tid];
    }
    __syncthreads();

    int warp = tid >> 5, lane = tid & 31;
    int lane2 = lane * 2;

    for (int row0 = blockIdx.x * 32 + warp * 4; row0 < NN; row0 += gridDim.x * 32) {
        float xr[2][4];   // [pair][(x_r0_d0, x_r1_d0, x_r0_d1, x_r1_d1)]

        // ---- stage: softmax rows + x rows, pair-packed ----
#pragma unroll
        for (int p = 0; p < 2; p++) {
            float s0[2], s1[2];
#pragma unroll
            for (int r = 0; r < 2; r++) {
                int row = row0 + p * 2 + r;
                unsigned hraw = *(const unsigned*)(g_gp + (size_t)row * D + lane2);
                float2 v = __half22float2(*(const __half2*)&hraw);
                float m = fmaxf(v.x, v.y);
#pragma unroll
                for (int o = 16; o; o >>= 1)
                    m = fmaxf(m, __shfl_xor_sync(0xffffffffu, m, o));
                float e0 = __expf(v.x - m), e1 = __expf(v.y - m);
                float s = e0 + e1;
#pragma unroll
                for (int o = 16; o; o >>= 1)
                    s += __shfl_xor_sync(0xffffffffu, s, o);
                float inv = 1.0f / s;
                s0[r] = e0 * inv;
                s1[r] = e1 * inv;
                float2 vx = *(const float2*)(xc_src + (size_t)row * D + lane2);
                xr[p][r]     = vx.x;
                xr[p][r + 2] = vx.y;
            }
            *(float4*)&SP[warp][p][lane2 * 2] = make_float4(s0[0], s0[1], s1[0], s1[1]);
            *(float4*)&XP[warp][p][lane2 * 2] =
                make_float4(xr[p][0], xr[p][1], xr[p][2], xr[p][3]);
        }
        __syncwarp();

        // ---- fc1: 4 rows, packed across each row pair ----
        ull a00 = 0ull, a01 = 0ull, a10 = 0ull, a11 = 0ull;
#pragma unroll 16
        for (int d = 0; d < 64; d++) {
            ull w = *(const ull*)&Wt1[d * 64 + lane2];
            float wlo, whi;
            UNPACK2(wlo, whi, w);
            ull w0d, w1d;
            PACK2(w0d, wlo, wlo);
            PACK2(w1d, whi, whi);
            ull sp0 = *(const ull*)&SP[warp][0][d * 2];
            ull sp1 = *(const ull*)&SP[warp][1][d * 2];
            FFMA2(a00, sp0, w0d);
            FFMA2(a01, sp0, w1d);
            FFMA2(a10, sp1, w0d);
            FFMA2(a11, sp1, w1d);
        }
        {
            ulonglong2 n0; n0.x = a00; n0.y = a01;
            ulonglong2 n1; n1.x = a10; n1.y = a11;
            *(ulonglong2*)&NP[warp][0][lane2 * 2] = n0;
            *(ulonglong2*)&NP[warp][1][lane2 * 2] = n1;
        }
        __syncwarp();

        // ---- fusion GEMVs: hidden for x and node, both pairs ----
        ull bj0, bj1;
        PACK2(bj0, b1s[lane2], b1s[lane2]);
        PACK2(bj1, b1s[lane2 + 1], b1s[lane2 + 1]);
        ull hx00 = bj0, hx01 = bj1, hx10 = bj0, hx11 = bj1;
        ull hn00 = bj0, hn01 = bj1, hn10 = bj0, hn11 = bj1;
#pragma unroll 16
        for (int d = 0; d < 64; d++) {
            ull w = *(const ull*)&Wtf[d * 64 + lane2];
            float wlo, whi;
            UNPACK2(wlo, whi, w);
            ull v0d, v1d;
            PACK2(v0d, wlo, wlo);
            PACK2(v1d, whi, whi);
            ull x0 = *(const ull*)&XP[warp][0][d * 2];
            ull x1 = *(const ull*)&XP[warp][1][d * 2];
            ull n0 = *(const ull*)&NP[warp][0][d * 2];
            ull n1 = *(const ull*)&NP[warp][1][d * 2];
            FFMA2(hx00, x0, v0d);
            FFMA2(hx01, x0, v1d);
            FFMA2(hx10, x1, v0d);
            FFMA2(hx11, x1, v1d);
            FFMA2(hn00, n0, v0d);
            FFMA2(hn01, n0, v1d);
            FFMA2(hn10, n1, v0d);
            FFMA2(hn11, n1, v1d);
        }

        // ---- scores, gate, blend, stores (per pair) ----
        float w2a = w2s[lane2], w2b = w2s[lane2 + 1];
        ull haccx[2][2] = {{hx00, hx01}, {hx10, hx11}};
        ull haccn[2][2] = {{hn00, hn01}, {hn10, hn11}};
        ull naccs[2][2] = {{a00, a01}, {a10, a11}};
        float bb0 = biass[lane2], bb1 = biass[lane2 + 1];
#pragma unroll
        for (int p = 0; p < 2; p++) {
            float hx0lo, hx0hi, hx1lo, hx1hi, hn0lo, hn0hi, hn1lo, hn1hi;
            UNPACK2(hx0lo, hx0hi, haccx[p][0]);
            UNPACK2(hx1lo, hx1hi, haccx[p][1]);
            UNPACK2(hn0lo, hn0hi, haccn[p][0]);
            UNPACK2(hn1lo, hn1hi, haccn[p][1]);
            float sxr0 = tanhf_fast(hx0lo) * w2a + tanhf_fast(hx1lo) * w2b;
            float sxr1 = tanhf_fast(hx0hi) * w2a + tanhf_fast(hx1hi) * w2b;
            float snr0 = tanhf_fast(hn0lo) * w2a + tanhf_fast(hn1lo) * w2b;
            float snr1 = tanhf_fast(hn0hi) * w2a + tanhf_fast(hn1hi) * w2b;
#pragma unroll
            for (int o = 16; o; o >>= 1) {
                sxr0 += __shfl_xor_sync(0xffffffffu, sxr0, o);
                sxr1 += __shfl_xor_sync(0xffffffffu, sxr1, o);
                snr0 += __shfl_xor_sync(0xffffffffu, snr0, o);
                snr1 += __shfl_xor_sync(0xffffffffu, snr1, o);
            }
            float aR0 = 1.0f / (1.0f + __expf(snr0 - sxr0));
            float aR1 = 1.0f / (1.0f + __expf(snr1 - sxr1));

            float n0lo, n0hi, n1lo, n1hi;
            UNPACK2(n0lo, n0hi, naccs[p][0]);
            UNPACK2(n1lo, n1hi, naccs[p][1]);

            int rowA = row0 + p * 2;
            int rowB = rowA + 1;
            float oA0 = aR0 * xr[p][0] + (1.f - aR0) * n0lo;
            float oA1 = aR0 * xr[p][2] + (1.f - aR0) * n1lo;
            float oB0 = aR1 * xr[p][1] + (1.f - aR1) * n0hi;
            float oB1 = aR1 * xr[p][3] + (1.f - aR1) * n1hi;

            *(float2*)(out_nodes + (size_t)rowA * D + lane2) = make_float2(oA0, oA1);
            *(float2*)(g_xc + (size_t)rowA * D + lane2)      = make_float2(oA0, oA1);
            *(float2*)(out_nodes + (size_t)rowB * D + lane2) = make_float2(oB0, oB1);
            *(float2*)(g_xc + (size_t)rowB * D + lane2)      = make_float2(oB0, oB1);
            if (knext >= 0) {
                float dA = __ldg(g_dinv + knext * NN + rowA);
                float dB = __ldg(g_dinv + knext * NN + rowB);
                *(__half2*)(g_gh + (size_t)rowA * D + lane2) = __floats2half2_rn(
                    dA * (fmaxf(oA0, 0.f) + bb0), dA * (fmaxf(oA1, 0.f) + bb1));
                *(__half2*)(g_gh + (size_t)rowB * D + lane2) = __floats2half2_rn(
                    dB * (fmaxf(oB0, 0.f) + bb0), dB * (fmaxf(oB1, 0.f) + bb1));
            }
        }
    }
}

// ---------------- launch ------------------------------------------------------
extern "C" void kernel_launch(void* const* d_in, const int* in_sizes, int n_in,
                              void* d_out, int out_size) {
    const float* x         = (const float*)d_in[0];
    const float* hgc1_bias = (const float*)d_in[1];
    const float* fc1_W     = (const float*)d_in[2];
    const float* fus_l1_W  = (const float*)d_in[3];
    const float* fus_l1_b  = (const float*)d_in[4];
    const float* fus_l2_W  = (const float*)d_in[5];
    // d_in[6] = fus_l2_b : cancels in the 2-way softmax
    const int* rows = (const int*)d_in[7];
    const int* cols = (const int*)d_in[8];

    float* out_nodes = (float*)d_out;
    float* out_edges = (float*)d_out + (size_t)K * NN * D;

    float* xc_p = nullptr;
    __half *gh_p = nullptr, *eh_p = nullptr, *gp_p = nullptr;
    int* cur_p = nullptr;
    cudaGetSymbolAddress((void**)&xc_p, g_xc);
    cudaGetSymbolAddress((void**)&gh_p, g_gh);
    cudaGetSymbolAddress((void**)&eh_p, g_eh);
    cudaGetSymbolAddress((void**)&gp_p, g_gp);
    cudaGetSymbolAddress((void**)&cur_p, g_cursor);

    // bucket-CSR build: memset + fill; dinv fused with g_gh init
    cudaMemsetAsync(cur_p, 0, (size_t)NTOT * sizeof(int));
    fill_bucket_kernel<<<(K * E + 255) / 256, 256>>>(rows, cols);
    dinv_g_kernel<<<(NN * 16 + 255) / 256, 256>>>(x, hgc1_bias);

    const int SPMM_BLOCKS = NN / 8;     // 12500 (warp per row)
    const int MEGA_BLOCKS = 592;        // persistent grid-stride, 4 CTAs/SM

    for (int k = 0; k < K; k++) {
        float* edge_k = out_edges + (size_t)k * NN * D;
        const float* xc_src = (k == 0) ? x : xc_p;
        // spmm1: edge = Â gh (fp32 out) ; g_eh = dinv ⊙ edge (fp16, extra di)
        gather_kernel<<<SPMM_BLOCKS, 256>>>(gh_p, edge_k, eh_p, 1, k);
        // spmm2: node_pre = Â (dinv ⊙ edge) -> g_gp (fp16 only)
        gather_kernel<<<SPMM_BLOCKS, 256>>>(eh_p, nullptr, gp_p, 0, k);
        // epilogue: softmax + fc1 + fusion gate (+ gh for next step)
        mega_kernel<<<MEGA_BLOCKS, 256>>>(
            fc1_W, fus_l1_W, fus_l1_b, fus_l2_W, hgc1_bias, xc_src,
            out_nodes + (size_t)k * NN * D, (k + 1 < K) ? (k + 1) : -1);
    }
}